// round 3
// baseline (speedup 1.0000x reference)
#include <cuda_runtime.h>
#include <cuda_bf16.h>

// Merged multi-hot embedding bag, sum pooling.
// B=32768, NT=26 tables, 214 packed index columns, DIM=128 fp32.
// Output: [B, 26*128] fp32.
//
// 16 warp-jobs per sample, but job id varies SLOWEST across gwarps so every
// warp in a block runs the same job type (uniform duration, shared table rows):
//   gwarp = j * BATCH + b
//   jobs 0..14 : the 15 multi-hot tables (hots >= 2), one warp each
//   job  15    : all 11 singleton tables fused into one warp

#define BATCH 32768
#define NT 26
#define TOTAL_COLS 214
#define DIM 128
#define NJOBS 16

// multi-hot tables: table id, hot count, start column
__constant__ int c_mt[15] = {0,1,3,4,9,10,11,13,14,15,19,20,21,22,23};
__constant__ int c_mh[15] = {3,2,2,6,7,3,8,6,9,5,12,100,27,10,3};
__constant__ int c_ms[15] = {0,3,6,8,18,25,28,37,43,52,60,72,172,199,209};
// singleton tables: packed column per lane
__constant__ int c_sc[11] = {5,14,15,16,17,36,57,58,59,212,213};

#define ROWPTR(i) ((const float4*)(weights + (long long)(i) * DIM) + lane)

__global__ __launch_bounds__(256)
void merged_embed_bag_kernel(const int* __restrict__ indices,
                             const float* __restrict__ weights,
                             float* __restrict__ out)
{
    const int gwarp = blockIdx.x * (blockDim.x >> 5) + (threadIdx.x >> 5);
    const int lane  = threadIdx.x & 31;
    const int b = gwarp & (BATCH - 1);   // sample (fast axis -> adjacent within block)
    const int j = gwarp >> 15;           // job type (uniform within block)
    if (j >= NJOBS) return;

    const int* rowidx = indices + (long long)b * TOTAL_COLS;
    float* orow = out + (long long)b * (NT * DIM);

    if (j < 15) {
        // ---- multi-hot table job ----
        const int t = c_mt[j];
        const int h = c_mh[j];
        const int s = c_ms[j];
        float4 acc = make_float4(0.f, 0.f, 0.f, 0.f);

        if (h <= 32) {
            // one coalesced index load, broadcast via shfl
            int iv = 0;
            if (lane < h) iv = __ldg(rowidx + s + lane);
            int k = 0;
            for (; k + 8 <= h; k += 8) {
                int i0 = __shfl_sync(0xffffffffu, iv, k);
                int i1 = __shfl_sync(0xffffffffu, iv, k + 1);
                int i2 = __shfl_sync(0xffffffffu, iv, k + 2);
                int i3 = __shfl_sync(0xffffffffu, iv, k + 3);
                int i4 = __shfl_sync(0xffffffffu, iv, k + 4);
                int i5 = __shfl_sync(0xffffffffu, iv, k + 5);
                int i6 = __shfl_sync(0xffffffffu, iv, k + 6);
                int i7 = __shfl_sync(0xffffffffu, iv, k + 7);
                float4 a0 = __ldg(ROWPTR(i0));
                float4 a1 = __ldg(ROWPTR(i1));
                float4 a2 = __ldg(ROWPTR(i2));
                float4 a3 = __ldg(ROWPTR(i3));
                float4 a4 = __ldg(ROWPTR(i4));
                float4 a5 = __ldg(ROWPTR(i5));
                float4 a6 = __ldg(ROWPTR(i6));
                float4 a7 = __ldg(ROWPTR(i7));
                acc.x += ((a0.x + a1.x) + (a2.x + a3.x)) + ((a4.x + a5.x) + (a6.x + a7.x));
                acc.y += ((a0.y + a1.y) + (a2.y + a3.y)) + ((a4.y + a5.y) + (a6.y + a7.y));
                acc.z += ((a0.z + a1.z) + (a2.z + a3.z)) + ((a4.z + a5.z) + (a6.z + a7.z));
                acc.w += ((a0.w + a1.w) + (a2.w + a3.w)) + ((a4.w + a5.w) + (a6.w + a7.w));
            }
            for (; k + 4 <= h; k += 4) {
                int i0 = __shfl_sync(0xffffffffu, iv, k);
                int i1 = __shfl_sync(0xffffffffu, iv, k + 1);
                int i2 = __shfl_sync(0xffffffffu, iv, k + 2);
                int i3 = __shfl_sync(0xffffffffu, iv, k + 3);
                float4 a0 = __ldg(ROWPTR(i0));
                float4 a1 = __ldg(ROWPTR(i1));
                float4 a2 = __ldg(ROWPTR(i2));
                float4 a3 = __ldg(ROWPTR(i3));
                acc.x += (a0.x + a1.x) + (a2.x + a3.x);
                acc.y += (a0.y + a1.y) + (a2.y + a3.y);
                acc.z += (a0.z + a1.z) + (a2.z + a3.z);
                acc.w += (a0.w + a1.w) + (a2.w + a3.w);
            }
            for (; k < h; k++) {
                int i0 = __shfl_sync(0xffffffffu, iv, k);
                float4 a0 = __ldg(ROWPTR(i0));
                acc.x += a0.x; acc.y += a0.y; acc.z += a0.z; acc.w += a0.w;
            }
        } else {
            // table 20: h == 100 = 3*32 + 4; 32 indices per round
            #pragma unroll
            for (int r = 0; r < 4; r++) {
                const int cnt = (r < 3) ? 32 : 4;
                int iv = 0;
                if (lane < cnt) iv = __ldg(rowidx + s + r * 32 + lane);
                int k = 0;
                for (; k + 8 <= cnt; k += 8) {
                    int i0 = __shfl_sync(0xffffffffu, iv, k);
                    int i1 = __shfl_sync(0xffffffffu, iv, k + 1);
                    int i2 = __shfl_sync(0xffffffffu, iv, k + 2);
                    int i3 = __shfl_sync(0xffffffffu, iv, k + 3);
                    int i4 = __shfl_sync(0xffffffffu, iv, k + 4);
                    int i5 = __shfl_sync(0xffffffffu, iv, k + 5);
                    int i6 = __shfl_sync(0xffffffffu, iv, k + 6);
                    int i7 = __shfl_sync(0xffffffffu, iv, k + 7);
                    float4 a0 = __ldg(ROWPTR(i0));
                    float4 a1 = __ldg(ROWPTR(i1));
                    float4 a2 = __ldg(ROWPTR(i2));
                    float4 a3 = __ldg(ROWPTR(i3));
                    float4 a4 = __ldg(ROWPTR(i4));
                    float4 a5 = __ldg(ROWPTR(i5));
                    float4 a6 = __ldg(ROWPTR(i6));
                    float4 a7 = __ldg(ROWPTR(i7));
                    acc.x += ((a0.x + a1.x) + (a2.x + a3.x)) + ((a4.x + a5.x) + (a6.x + a7.x));
                    acc.y += ((a0.y + a1.y) + (a2.y + a3.y)) + ((a4.y + a5.y) + (a6.y + a7.y));
                    acc.z += ((a0.z + a1.z) + (a2.z + a3.z)) + ((a4.z + a5.z) + (a6.z + a7.z));
                    acc.w += ((a0.w + a1.w) + (a2.w + a3.w)) + ((a4.w + a5.w) + (a6.w + a7.w));
                }
                for (; k + 4 <= cnt; k += 4) {
                    int i0 = __shfl_sync(0xffffffffu, iv, k);
                    int i1 = __shfl_sync(0xffffffffu, iv, k + 1);
                    int i2 = __shfl_sync(0xffffffffu, iv, k + 2);
                    int i3 = __shfl_sync(0xffffffffu, iv, k + 3);
                    float4 a0 = __ldg(ROWPTR(i0));
                    float4 a1 = __ldg(ROWPTR(i1));
                    float4 a2 = __ldg(ROWPTR(i2));
                    float4 a3 = __ldg(ROWPTR(i3));
                    acc.x += (a0.x + a1.x) + (a2.x + a3.x);
                    acc.y += (a0.y + a1.y) + (a2.y + a3.y);
                    acc.z += (a0.z + a1.z) + (a2.z + a3.z);
                    acc.w += (a0.w + a1.w) + (a2.w + a3.w);
                }
            }
        }
        __stcs((float4*)(orow + t * DIM) + lane, acc);
    } else {
        // ---- fused singleton job: 11 independent copy lookups ----
        int iv = 0;
        if (lane < 11) iv = __ldg(rowidx + c_sc[lane]);

        int i0 = __shfl_sync(0xffffffffu, iv, 0);
        int i1 = __shfl_sync(0xffffffffu, iv, 1);
        int i2 = __shfl_sync(0xffffffffu, iv, 2);
        int i3 = __shfl_sync(0xffffffffu, iv, 3);
        int i4 = __shfl_sync(0xffffffffu, iv, 4);
        int i5 = __shfl_sync(0xffffffffu, iv, 5);
        int i6 = __shfl_sync(0xffffffffu, iv, 6);
        int i7 = __shfl_sync(0xffffffffu, iv, 7);
        int i8 = __shfl_sync(0xffffffffu, iv, 8);
        int i9 = __shfl_sync(0xffffffffu, iv, 9);
        int i10 = __shfl_sync(0xffffffffu, iv, 10);

        float4 a0 = __ldg(ROWPTR(i0));
        float4 a1 = __ldg(ROWPTR(i1));
        float4 a2 = __ldg(ROWPTR(i2));
        float4 a3 = __ldg(ROWPTR(i3));
        float4 a4 = __ldg(ROWPTR(i4));
        float4 a5 = __ldg(ROWPTR(i5));
        float4 a6 = __ldg(ROWPTR(i6));
        float4 a7 = __ldg(ROWPTR(i7));
        float4 a8 = __ldg(ROWPTR(i8));
        float4 a9 = __ldg(ROWPTR(i9));
        float4 a10 = __ldg(ROWPTR(i10));

        __stcs((float4*)(orow +  2 * DIM) + lane, a0);
        __stcs((float4*)(orow +  5 * DIM) + lane, a1);
        __stcs((float4*)(orow +  6 * DIM) + lane, a2);
        __stcs((float4*)(orow +  7 * DIM) + lane, a3);
        __stcs((float4*)(orow +  8 * DIM) + lane, a4);
        __stcs((float4*)(orow + 12 * DIM) + lane, a5);
        __stcs((float4*)(orow + 16 * DIM) + lane, a6);
        __stcs((float4*)(orow + 17 * DIM) + lane, a7);
        __stcs((float4*)(orow + 18 * DIM) + lane, a8);
        __stcs((float4*)(orow + 24 * DIM) + lane, a9);
        __stcs((float4*)(orow + 25 * DIM) + lane, a10);
    }
}

extern "C" void kernel_launch(void* const* d_in, const int* in_sizes, int n_in,
                              void* d_out, int out_size)
{
    const int* indices = nullptr;
    const float* weights = nullptr;
    const long long idx_elems = (long long)BATCH * TOTAL_COLS;
    for (int i = 0; i < n_in; i++) {
        if ((long long)in_sizes[i] == idx_elems) indices = (const int*)d_in[i];
        else weights = (const float*)d_in[i];
    }
    float* out = (float*)d_out;

    const int threads = 256;
    const int warps_per_block = threads / 32;
    const long long total_warps = (long long)BATCH * NJOBS;  // 524288
    const int blocks = (int)((total_warps + warps_per_block - 1) / warps_per_block);

    merged_embed_bag_kernel<<<blocks, threads>>>(indices, weights, out);
}

// round 4
// speedup vs baseline: 1.3215x; 1.3215x over previous
#include <cuda_runtime.h>
#include <cuda_bf16.h>

// Merged multi-hot embedding bag, sum pooling.
// B=32768, NT=26 tables, 214 packed index columns, DIM=128 fp32.
// Output: [B, 26*128] fp32.
//
// Duration-balanced warp jobs:
//  Heavy block (blockIdx < B): ONE sample, 8 warps:
//    w0..w3 : table 20 quarters (25 hots each), combined via smem
//    w4     : t21 (27)
//    w5     : t19 (12) + t1 (2)
//    w6     : t22 (10) + t10 (3)
//    w7     : t14 (9) + t0 (3)
//  Light block (blockIdx >= B): TWO samples, 4 warps each:
//    v0     : t11 (8) + t3 (2) + single t2
//    v1     : t9 (7) + t15 (5)
//    v2     : t4 (6) + t13 (6)
//    v3     : t23 (3) + 10 singles

#define BATCH 32768
#define NT 26
#define TOTAL_COLS 214
#define DIM 128

// columns of the 10 singles handled by light-warp v3, and their table ids
__constant__ int c_s3col[10] = {14,15,16,17,36,57,58,59,212,213};
__constant__ int c_s3tab[10] = {5,6,7,8,12,16,17,18,24,25};

#define ROWF4(i) ((const float4*)(weights + (long long)(i) * DIM) + lane)

__device__ __forceinline__ float4 gather_sum(const int* __restrict__ idxp, int h,
                                             const float* __restrict__ weights, int lane)
{
    // h <= 32: one coalesced index load, broadcast via shfl
    int iv = 0;
    if (lane < h) iv = __ldg(idxp + lane);
    float4 acc = make_float4(0.f, 0.f, 0.f, 0.f);
    int k = 0;
    for (; k + 4 <= h; k += 4) {
        int i0 = __shfl_sync(0xffffffffu, iv, k);
        int i1 = __shfl_sync(0xffffffffu, iv, k + 1);
        int i2 = __shfl_sync(0xffffffffu, iv, k + 2);
        int i3 = __shfl_sync(0xffffffffu, iv, k + 3);
        float4 a0 = __ldg(ROWF4(i0));
        float4 a1 = __ldg(ROWF4(i1));
        float4 a2 = __ldg(ROWF4(i2));
        float4 a3 = __ldg(ROWF4(i3));
        acc.x += (a0.x + a1.x) + (a2.x + a3.x);
        acc.y += (a0.y + a1.y) + (a2.y + a3.y);
        acc.z += (a0.z + a1.z) + (a2.z + a3.z);
        acc.w += (a0.w + a1.w) + (a2.w + a3.w);
    }
    for (; k < h; k++) {
        int i0 = __shfl_sync(0xffffffffu, iv, k);
        float4 a0 = __ldg(ROWF4(i0));
        acc.x += a0.x; acc.y += a0.y; acc.z += a0.z; acc.w += a0.w;
    }
    return acc;
}

__device__ __forceinline__ void bag_store(const int* __restrict__ rowidx, int s, int h,
                                          const float* __restrict__ weights, int lane,
                                          float* __restrict__ orow, int t)
{
    float4 acc = gather_sum(rowidx + s, h, weights, lane);
    __stcs((float4*)(orow + t * DIM) + lane, acc);
}

__global__ __launch_bounds__(256)
void merged_embed_bag_kernel(const int* __restrict__ indices,
                             const float* __restrict__ weights,
                             float* __restrict__ out)
{
    __shared__ float4 sp[3][32];   // table-20 partials from warps 1..3

    const int blk  = blockIdx.x;
    const int w    = threadIdx.x >> 5;
    const int lane = threadIdx.x & 31;
    const bool heavy = (blk < BATCH);   // heavy blocks dispatched first

    if (heavy) {
        const int b = blk;
        const int* rowidx = indices + (long long)b * TOTAL_COLS;
        float* orow = out + (long long)b * (NT * DIM);

        float4 t20acc;
        if (w < 4) {
            // table 20 quarter: cols [72 + 25*w, 72 + 25*w + 25)
            t20acc = gather_sum(rowidx + 72 + 25 * w, 25, weights, lane);
            if (w != 0) sp[w - 1][lane] = t20acc;
        } else if (w == 4) {
            bag_store(rowidx, 172, 27, weights, lane, orow, 21);
        } else if (w == 5) {
            bag_store(rowidx, 60, 12, weights, lane, orow, 19);
            bag_store(rowidx, 3, 2, weights, lane, orow, 1);
        } else if (w == 6) {
            bag_store(rowidx, 199, 10, weights, lane, orow, 22);
            bag_store(rowidx, 25, 3, weights, lane, orow, 10);
        } else {
            bag_store(rowidx, 43, 9, weights, lane, orow, 14);
            bag_store(rowidx, 0, 3, weights, lane, orow, 0);
        }

        __syncthreads();   // block-uniform path

        if (w == 0) {
            float4 p0 = sp[0][lane];
            float4 p1 = sp[1][lane];
            float4 p2 = sp[2][lane];
            t20acc.x += (p0.x + p1.x) + p2.x;
            t20acc.y += (p0.y + p1.y) + p2.y;
            t20acc.z += (p0.z + p1.z) + p2.z;
            t20acc.w += (p0.w + p1.w) + p2.w;
            __stcs((float4*)(orow + 20 * DIM) + lane, t20acc);
        }
    } else {
        // light block: two samples, 4 warps each
        const int p = blk - BATCH;
        const int b = (p << 1) | (w >> 2);
        const int v = w & 3;
        const int* rowidx = indices + (long long)b * TOTAL_COLS;
        float* orow = out + (long long)b * (NT * DIM);

        if (v == 0) {
            bag_store(rowidx, 28, 8, weights, lane, orow, 11);
            bag_store(rowidx, 6, 2, weights, lane, orow, 3);
            // single: table 2 at col 5
            int i0 = __ldg(rowidx + 5);
            float4 a0 = __ldg(ROWF4(i0));
            __stcs((float4*)(orow + 2 * DIM) + lane, a0);
        } else if (v == 1) {
            bag_store(rowidx, 18, 7, weights, lane, orow, 9);
            bag_store(rowidx, 52, 5, weights, lane, orow, 15);
        } else if (v == 2) {
            bag_store(rowidx, 8, 6, weights, lane, orow, 4);
            bag_store(rowidx, 37, 6, weights, lane, orow, 13);
        } else {
            bag_store(rowidx, 209, 3, weights, lane, orow, 23);
            // 10 singles: coalesced idx load + shfl, then 10 independent copies
            int iv = 0;
            if (lane < 10) iv = __ldg(rowidx + c_s3col[lane]);
            int i0 = __shfl_sync(0xffffffffu, iv, 0);
            int i1 = __shfl_sync(0xffffffffu, iv, 1);
            int i2 = __shfl_sync(0xffffffffu, iv, 2);
            int i3 = __shfl_sync(0xffffffffu, iv, 3);
            int i4 = __shfl_sync(0xffffffffu, iv, 4);
            float4 a0 = __ldg(ROWF4(i0));
            float4 a1 = __ldg(ROWF4(i1));
            float4 a2 = __ldg(ROWF4(i2));
            float4 a3 = __ldg(ROWF4(i3));
            float4 a4 = __ldg(ROWF4(i4));
            __stcs((float4*)(orow +  5 * DIM) + lane, a0);
            __stcs((float4*)(orow +  6 * DIM) + lane, a1);
            __stcs((float4*)(orow +  7 * DIM) + lane, a2);
            __stcs((float4*)(orow +  8 * DIM) + lane, a3);
            __stcs((float4*)(orow + 12 * DIM) + lane, a4);
            int i5 = __shfl_sync(0xffffffffu, iv, 5);
            int i6 = __shfl_sync(0xffffffffu, iv, 6);
            int i7 = __shfl_sync(0xffffffffu, iv, 7);
            int i8 = __shfl_sync(0xffffffffu, iv, 8);
            int i9 = __shfl_sync(0xffffffffu, iv, 9);
            float4 a5 = __ldg(ROWF4(i5));
            float4 a6 = __ldg(ROWF4(i6));
            float4 a7 = __ldg(ROWF4(i7));
            float4 a8 = __ldg(ROWF4(i8));
            float4 a9 = __ldg(ROWF4(i9));
            __stcs((float4*)(orow + 16 * DIM) + lane, a5);
            __stcs((float4*)(orow + 17 * DIM) + lane, a6);
            __stcs((float4*)(orow + 18 * DIM) + lane, a7);
            __stcs((float4*)(orow + 24 * DIM) + lane, a8);
            __stcs((float4*)(orow + 25 * DIM) + lane, a9);
        }
    }
}

extern "C" void kernel_launch(void* const* d_in, const int* in_sizes, int n_in,
                              void* d_out, int out_size)
{
    const int* indices = nullptr;
    const float* weights = nullptr;
    const long long idx_elems = (long long)BATCH * TOTAL_COLS;
    for (int i = 0; i < n_in; i++) {
        if ((long long)in_sizes[i] == idx_elems) indices = (const int*)d_in[i];
        else weights = (const float*)d_in[i];
    }
    float* out = (float*)d_out;

    const int threads = 256;
    const int blocks = BATCH + BATCH / 2;   // 32768 heavy + 16384 light = 49152

    merged_embed_bag_kernel<<<blocks, threads>>>(indices, weights, out);
}

// round 5
// speedup vs baseline: 1.3899x; 1.0517x over previous
#include <cuda_runtime.h>
#include <cuda_bf16.h>

// Merged multi-hot embedding bag, sum pooling.
// B=32768, NT=26 tables, 214 packed index columns, DIM=128 fp32.
// Output: [B, 26*128] fp32.
//
// Duration-balanced warp jobs:
//  Heavy block (blockIdx < B): ONE sample, 8 warps:
//    w0..w3 : table 20 quarters (25 hots each), combined via smem
//             (subset barrier: bar.sync 1,128 among warps 0..3 ONLY)
//    w4     : t21 (27)
//    w5     : t19 (12) + t1 (2)
//    w6     : t22 (10) + t10 (3)
//    w7     : t14 (9) + t0 (3)
//  Light block (blockIdx >= B): TWO samples, 4 warps each:
//    v0     : t11 (8) + t3 (2) + single t2
//    v1     : t9 (7) + t15 (5)
//    v2     : t4 (6) + t13 (6)
//    v3     : t23 (3) + 10 singles

#define BATCH 32768
#define NT 26
#define TOTAL_COLS 214
#define DIM 128

// columns of the 10 singles handled by light-warp v3
__constant__ int c_s3col[10] = {14,15,16,17,36,57,58,59,212,213};

#define ROWF4(i) ((const float4*)(weights + (long long)(i) * DIM) + lane)

__device__ __forceinline__ float4 gather_sum(const int* __restrict__ idxp, int h,
                                             const float* __restrict__ weights, int lane)
{
    // h <= 32: one coalesced index load, broadcast via shfl
    int iv = 0;
    if (lane < h) iv = __ldg(idxp + lane);
    float4 acc = make_float4(0.f, 0.f, 0.f, 0.f);
    int k = 0;
    for (; k + 4 <= h; k += 4) {
        int i0 = __shfl_sync(0xffffffffu, iv, k);
        int i1 = __shfl_sync(0xffffffffu, iv, k + 1);
        int i2 = __shfl_sync(0xffffffffu, iv, k + 2);
        int i3 = __shfl_sync(0xffffffffu, iv, k + 3);
        float4 a0 = __ldg(ROWF4(i0));
        float4 a1 = __ldg(ROWF4(i1));
        float4 a2 = __ldg(ROWF4(i2));
        float4 a3 = __ldg(ROWF4(i3));
        acc.x += (a0.x + a1.x) + (a2.x + a3.x);
        acc.y += (a0.y + a1.y) + (a2.y + a3.y);
        acc.z += (a0.z + a1.z) + (a2.z + a3.z);
        acc.w += (a0.w + a1.w) + (a2.w + a3.w);
    }
    for (; k < h; k++) {
        int i0 = __shfl_sync(0xffffffffu, iv, k);
        float4 a0 = __ldg(ROWF4(i0));
        acc.x += a0.x; acc.y += a0.y; acc.z += a0.z; acc.w += a0.w;
    }
    return acc;
}

__device__ __forceinline__ void bag_store(const int* __restrict__ rowidx, int s, int h,
                                          const float* __restrict__ weights, int lane,
                                          float* __restrict__ orow, int t)
{
    float4 acc = gather_sum(rowidx + s, h, weights, lane);
    __stcs((float4*)(orow + t * DIM) + lane, acc);
}

__global__ __launch_bounds__(256, 7)
void merged_embed_bag_kernel(const int* __restrict__ indices,
                             const float* __restrict__ weights,
                             float* __restrict__ out)
{
    __shared__ float4 sp[3][32];   // table-20 partials from warps 1..3

    const int blk  = blockIdx.x;
    const int w    = threadIdx.x >> 5;
    const int lane = threadIdx.x & 31;
    const bool heavy = (blk < BATCH);   // heavy blocks dispatched first

    if (heavy) {
        const int b = blk;
        const int* rowidx = indices + (long long)b * TOTAL_COLS;
        float* orow = out + (long long)b * (NT * DIM);

        if (w < 4) {
            // table 20 quarter: cols [72 + 25*w, 72 + 25*w + 25)
            float4 t20acc = gather_sum(rowidx + 72 + 25 * w, 25, weights, lane);
            if (w != 0) sp[w - 1][lane] = t20acc;
            // subset barrier: only warps 0..3 (128 threads) participate
            asm volatile("bar.sync 1, 128;" ::: "memory");
            if (w == 0) {
                float4 p0 = sp[0][lane];
                float4 p1 = sp[1][lane];
                float4 p2 = sp[2][lane];
                t20acc.x += (p0.x + p1.x) + p2.x;
                t20acc.y += (p0.y + p1.y) + p2.y;
                t20acc.z += (p0.z + p1.z) + p2.z;
                t20acc.w += (p0.w + p1.w) + p2.w;
                __stcs((float4*)(orow + 20 * DIM) + lane, t20acc);
            }
        } else if (w == 4) {
            bag_store(rowidx, 172, 27, weights, lane, orow, 21);
        } else if (w == 5) {
            bag_store(rowidx, 60, 12, weights, lane, orow, 19);
            bag_store(rowidx, 3, 2, weights, lane, orow, 1);
        } else if (w == 6) {
            bag_store(rowidx, 199, 10, weights, lane, orow, 22);
            bag_store(rowidx, 25, 3, weights, lane, orow, 10);
        } else {
            bag_store(rowidx, 43, 9, weights, lane, orow, 14);
            bag_store(rowidx, 0, 3, weights, lane, orow, 0);
        }
    } else {
        // light block: two samples, 4 warps each
        const int p = blk - BATCH;
        const int b = (p << 1) | (w >> 2);
        const int v = w & 3;
        const int* rowidx = indices + (long long)b * TOTAL_COLS;
        float* orow = out + (long long)b * (NT * DIM);

        if (v == 0) {
            bag_store(rowidx, 28, 8, weights, lane, orow, 11);
            bag_store(rowidx, 6, 2, weights, lane, orow, 3);
            // single: table 2 at col 5
            int i0 = __ldg(rowidx + 5);
            float4 a0 = __ldg(ROWF4(i0));
            __stcs((float4*)(orow + 2 * DIM) + lane, a0);
        } else if (v == 1) {
            bag_store(rowidx, 18, 7, weights, lane, orow, 9);
            bag_store(rowidx, 52, 5, weights, lane, orow, 15);
        } else if (v == 2) {
            bag_store(rowidx, 8, 6, weights, lane, orow, 4);
            bag_store(rowidx, 37, 6, weights, lane, orow, 13);
        } else {
            bag_store(rowidx, 209, 3, weights, lane, orow, 23);
            // 10 singles: coalesced idx load + shfl, then 10 independent copies
            int iv = 0;
            if (lane < 10) iv = __ldg(rowidx + c_s3col[lane]);
            int i0 = __shfl_sync(0xffffffffu, iv, 0);
            int i1 = __shfl_sync(0xffffffffu, iv, 1);
            int i2 = __shfl_sync(0xffffffffu, iv, 2);
            int i3 = __shfl_sync(0xffffffffu, iv, 3);
            int i4 = __shfl_sync(0xffffffffu, iv, 4);
            float4 a0 = __ldg(ROWF4(i0));
            float4 a1 = __ldg(ROWF4(i1));
            float4 a2 = __ldg(ROWF4(i2));
            float4 a3 = __ldg(ROWF4(i3));
            float4 a4 = __ldg(ROWF4(i4));
            __stcs((float4*)(orow +  5 * DIM) + lane, a0);
            __stcs((float4*)(orow +  6 * DIM) + lane, a1);
            __stcs((float4*)(orow +  7 * DIM) + lane, a2);
            __stcs((float4*)(orow +  8 * DIM) + lane, a3);
            __stcs((float4*)(orow + 12 * DIM) + lane, a4);
            int i5 = __shfl_sync(0xffffffffu, iv, 5);
            int i6 = __shfl_sync(0xffffffffu, iv, 6);
            int i7 = __shfl_sync(0xffffffffu, iv, 7);
            int i8 = __shfl_sync(0xffffffffu, iv, 8);
            int i9 = __shfl_sync(0xffffffffu, iv, 9);
            float4 a5 = __ldg(ROWF4(i5));
            float4 a6 = __ldg(ROWF4(i6));
            float4 a7 = __ldg(ROWF4(i7));
            float4 a8 = __ldg(ROWF4(i8));
            float4 a9 = __ldg(ROWF4(i9));
            __stcs((float4*)(orow + 16 * DIM) + lane, a5);
            __stcs((float4*)(orow + 17 * DIM) + lane, a6);
            __stcs((float4*)(orow + 18 * DIM) + lane, a7);
            __stcs((float4*)(orow + 24 * DIM) + lane, a8);
            __stcs((float4*)(orow + 25 * DIM) + lane, a9);
        }
    }
}

extern "C" void kernel_launch(void* const* d_in, const int* in_sizes, int n_in,
                              void* d_out, int out_size)
{
    const int* indices = nullptr;
    const float* weights = nullptr;
    const long long idx_elems = (long long)BATCH * TOTAL_COLS;
    for (int i = 0; i < n_in; i++) {
        if ((long long)in_sizes[i] == idx_elems) indices = (const int*)d_in[i];
        else weights = (const float*)d_in[i];
    }
    float* out = (float*)d_out;

    const int threads = 256;
    const int blocks = BATCH + BATCH / 2;   // 32768 heavy + 16384 light = 49152

    merged_embed_bag_kernel<<<blocks, threads>>>(indices, weights, out);
}